// round 5
// baseline (speedup 1.0000x reference)
#include <cuda_runtime.h>
#include <cstdint>

// ---------------- problem constants ----------------------------------------
#define Bq     16
#define NSEQ   1569            // 1 + 8*196
#define DMODEL 768
#define NH     12
#define DH     64
#define NF     8
#define NPF    196
#define MROWS  (Bq * NSEQ)     // 25104
#define QKVC   (3 * DMODEL)    // 2304

// scratch (no cudaMalloc allowed)
__device__ float g_qkv[(size_t)MROWS * QKVC];     // 231 MB
__device__ float g_attn[(size_t)MROWS * DMODEL];  // 77 MB
__device__ float g_x[(size_t)MROWS * DMODEL];     // tf32-rounded x
__device__ float g_wq[(size_t)DMODEL * QKVC];     // rounded w_qkv
__device__ float g_wp[(size_t)DMODEL * DMODEL];   // rounded w_proj

__device__ __forceinline__ uint32_t f2tf(float x) {
    uint32_t r;
    asm("cvt.rna.tf32.f32 %0, %1;" : "=r"(r) : "f"(x));
    return r;
}
__device__ __forceinline__ float f2tff(float x) { return __uint_as_float(f2tf(x)); }

__device__ __forceinline__ uint32_t s2u(const void* p) {
    return (uint32_t)__cvta_generic_to_shared(p);
}

#define MMA_TF32(c, a0,a1,a2,a3, b0,b1)                                          \
    asm volatile(                                                                 \
        "mma.sync.aligned.m16n8k8.row.col.f32.tf32.tf32.f32 "                     \
        "{%0,%1,%2,%3}, {%4,%5,%6,%7}, {%8,%9}, {%0,%1,%2,%3};"                   \
        : "+f"(c[0]), "+f"(c[1]), "+f"(c[2]), "+f"(c[3])                          \
        : "r"(a0), "r"(a1), "r"(a2), "r"(a3), "r"(b0), "r"(b1))

// ---------------- tf32 pre-round pass ---------------------------------------
__global__ __launch_bounds__(256) void round_tf32(
    const float* __restrict__ in, float* __restrict__ out, int n4)
{
    int i = blockIdx.x * 256 + threadIdx.x;
    if (i < n4) {
        float4 v = reinterpret_cast<const float4*>(in)[i];
        v.x = f2tff(v.x); v.y = f2tff(v.y); v.z = f2tff(v.z); v.w = f2tff(v.w);
        reinterpret_cast<float4*>(out)[i] = v;
    }
}

// ---------------- TF32 GEMM: cp.async 3-stage, 2 CTAs/SM --------------------
#define BM 128
#define BN 128
#define BK 32
#define ASTR 36
#define BSTR 136
#define ABUF (BM * ASTR)
#define BBUF (BK * BSTR)
#define STAGES 3
#define GEMM_SMEM (STAGES * (ABUF + BBUF) * 4)   // 107520 bytes

template <bool BIAS>
__global__ __launch_bounds__(256, 2) void gemm_tf32_ca(
    const float* __restrict__ A, const float* __restrict__ Bmat,
    const float* __restrict__ bias, float* __restrict__ C,
    int Mr, int Nc, int Kd)
{
    extern __shared__ float sm[];
    float* As = sm;
    float* Bs = sm + STAGES * ABUF;

    const int tid  = threadIdx.x;
    const int warp = tid >> 5, lane = tid & 31;
    const int gid  = lane >> 2, tig = lane & 3;
    const int wm   = (warp >> 1) * 32;
    const int wn   = (warp & 1) * 64;
    const int brow = blockIdx.y * BM;
    const int bcol = blockIdx.x * BN;

    float acc[2][8][4];
#pragma unroll
    for (int mi = 0; mi < 2; mi++)
#pragma unroll
        for (int ni = 0; ni < 8; ni++)
#pragma unroll
            for (int r = 0; r < 4; r++) acc[mi][ni][r] = 0.f;

    const int nkt = Kd / BK;

    auto issue = [&](int kt) {
        const int buf = kt % STAGES;
        float* Ab = As + buf * ABUF;
        float* Bb = Bs + buf * BBUF;
#pragma unroll
        for (int i = 0; i < 4; i++) {
            int cid = tid + i * 256;
            int row = cid >> 3, c4 = (cid & 7) << 2;
            const float* src = A + (long)(brow + row) * Kd + kt * BK + c4;
            int sz = (brow + row < Mr) ? 16 : 0;
            asm volatile("cp.async.cg.shared.global [%0], [%1], 16, %2;"
                         :: "r"(s2u(Ab + row * ASTR + c4)), "l"(src), "r"(sz));
        }
#pragma unroll
        for (int i = 0; i < 4; i++) {
            int cid = tid + i * 256;
            int kr = cid >> 5, c4 = (cid & 31) << 2;
            const float* src = Bmat + (long)(kt * BK + kr) * Nc + bcol + c4;
            asm volatile("cp.async.cg.shared.global [%0], [%1], 16;"
                         :: "r"(s2u(Bb + kr * BSTR + c4)), "l"(src));
        }
    };

    auto compute = [&](int buf) {
        const uint32_t* Ab = reinterpret_cast<const uint32_t*>(As + buf * ABUF);
        const uint32_t* Bb = reinterpret_cast<const uint32_t*>(Bs + buf * BBUF);
#pragma unroll
        for (int ks = 0; ks < 4; ks++) {
            const int k0 = ks * 8;
            uint32_t af[2][4], bf[8][2];
#pragma unroll
            for (int mi = 0; mi < 2; mi++) {
                const uint32_t* p = Ab + (wm + mi * 16 + gid) * ASTR + k0 + tig;
                af[mi][0] = p[0];
                af[mi][1] = p[8 * ASTR];
                af[mi][2] = p[4];
                af[mi][3] = p[8 * ASTR + 4];
            }
#pragma unroll
            for (int ni = 0; ni < 8; ni++) {
                const uint32_t* p = Bb + (k0 + tig) * BSTR + wn + ni * 8 + gid;
                bf[ni][0] = p[0];
                bf[ni][1] = p[4 * BSTR];
            }
#pragma unroll
            for (int mi = 0; mi < 2; mi++)
#pragma unroll
                for (int ni = 0; ni < 8; ni++)
                    MMA_TF32(acc[mi][ni], af[mi][0], af[mi][1], af[mi][2], af[mi][3],
                             bf[ni][0], bf[ni][1]);
        }
    };

#pragma unroll
    for (int s = 0; s < STAGES - 1; s++) {
        issue(s);
        asm volatile("cp.async.commit_group;");
    }

#pragma unroll 1
    for (int kt = 0; kt < nkt; kt++) {
        asm volatile("cp.async.wait_group %0;" :: "n"(STAGES - 2));
        __syncthreads();
        // issue next stage BEFORE compute: buffer (kt+2)%3 == (kt-1)%3 was
        // fully consumed before the barrier above, so overwrite is safe.
        if (kt + STAGES - 1 < nkt) {
            issue(kt + STAGES - 1);
            asm volatile("cp.async.commit_group;");
        }
        compute(kt % STAGES);
    }

#pragma unroll
    for (int mi = 0; mi < 2; mi++) {
        int r0 = brow + wm + mi * 16 + gid;
#pragma unroll
        for (int ni = 0; ni < 8; ni++) {
            int c0 = bcol + wn + ni * 8 + tig * 2;
            float bx = 0.f, by = 0.f;
            if (BIAS) { bx = bias[c0]; by = bias[c0 + 1]; }
            if (r0 < Mr) {
                float2 v = make_float2(acc[mi][ni][0] + bx, acc[mi][ni][1] + by);
                *reinterpret_cast<float2*>(C + (long)r0 * Nc + c0) = v;
            }
            if (r0 + 8 < Mr) {
                float2 v = make_float2(acc[mi][ni][2] + bx, acc[mi][ni][3] + by);
                *reinterpret_cast<float2*>(C + (long)(r0 + 8) * Nc + c0) = v;
            }
        }
    }
}

// ---------------- frame attention v2: 32-row warp tiles ---------------------
// 8 warps; warps 0..6 each own 32 query rows (warp 6: rows 192..223, only
// 192..195 real). Keys processed in 4 quarters {7,6,6,6} n-tiles of 8:
// S-quarter -> exp -> P^T to smem -> O accumulate. P^T stride 40 makes the
// O-phase A-fragment loads conflict-free (bank = 8*tig + gid).
#define KSTR  68
#define VSTR  72
#define PTSTR 40
#define QSTR  68
#define PT_WARP (56 * PTSTR)                 // 2240 floats (>= 32*68=2176 Q stage)
#define F_KS_OFF 0
#define F_VS_OFF (200 * KSTR)                // 13600
#define F_PT_OFF (F_VS_OFF + 200 * VSTR)     // 28000
#define F_SMEM   ((F_PT_OFF + 8 * PT_WARP) * 4)   // 183680 bytes

__global__ __launch_bounds__(256) void frame_attn_mma(
    const float* __restrict__ qkv, float* __restrict__ attn)
{
    extern __shared__ float smf[];
    float* Ks = smf + F_KS_OFF;   // [200][KSTR]
    float* Vs = smf + F_VS_OFF;   // [200][VSTR]

    const int tid  = threadIdx.x;
    const int warp = tid >> 5, lane = tid & 31;
    const int gid  = lane >> 2, tig = lane & 3;

    const int bid = blockIdx.x;           // (b*NH + h)*NF + fr
    const int fr  = bid & 7;
    const int h   = (bid >> 3) % NH;
    const int b   = bid / (NF * NH);

    const long rowbase = (long)b * NSEQ;
    const int  hoff    = h * DH;

    // cooperative K/V load with tf32 rounding; rows 197..199 zero-padded
    for (int idx = tid; idx < 200 * 16; idx += 256) {
        int j  = idx >> 4;
        int c4 = (idx & 15) << 2;
        float4 kk = make_float4(0.f, 0.f, 0.f, 0.f);
        float4 vv = make_float4(0.f, 0.f, 0.f, 0.f);
        if (j < 197) {
            int t = (j == 0) ? 0 : (1 + fr * NPF + j - 1);
            const float* src = qkv + (rowbase + t) * QKVC + hoff;
            kk = *reinterpret_cast<const float4*>(src + DMODEL + c4);
            vv = *reinterpret_cast<const float4*>(src + 2 * DMODEL + c4);
            kk.x = f2tff(kk.x); kk.y = f2tff(kk.y); kk.z = f2tff(kk.z); kk.w = f2tff(kk.w);
            vv.x = f2tff(vv.x); vv.y = f2tff(vv.y); vv.z = f2tff(vv.z); vv.w = f2tff(vv.w);
        }
        *reinterpret_cast<float4*>(&Ks[j * KSTR + c4]) = kk;
        *reinterpret_cast<float4*>(&Vs[j * VSTR + c4]) = vv;
    }
    __syncthreads();

    if (warp < 7) {
        const int base = warp * 32;
        float* Pw = smf + F_PT_OFF + warp * PT_WARP;
        const uint32_t* Ku = reinterpret_cast<const uint32_t*>(Ks);
        const uint32_t* Vu = reinterpret_cast<const uint32_t*>(Vs);
        uint32_t* PTw = reinterpret_cast<uint32_t*>(Pw);

        // ---- stage Q tile (32 x 64) into Pw [32][QSTR], coalesced ----
#pragma unroll
        for (int i = 0; i < 16; i++) {
            int idx = lane + i * 32;        // 0..511
            int row = idx >> 4;             // 0..31
            int c4  = (idx & 15) << 2;
            float4 v = make_float4(0.f, 0.f, 0.f, 0.f);
            int grow = base + row;
            if (grow < NPF) {
                const float* qp = qkv + (rowbase + 1 + fr * NPF + grow) * QKVC + hoff + c4;
                float4 u = *reinterpret_cast<const float4*>(qp);
                v.x = f2tff(u.x * 0.125f);
                v.y = f2tff(u.y * 0.125f);
                v.z = f2tff(u.z * 0.125f);
                v.w = f2tff(u.w * 0.125f);
            }
            *reinterpret_cast<float4*>(Pw + row * QSTR + c4) = v;
        }
        __syncwarp();

        // ---- Q fragments: af[kc][mi][4] ----
        uint32_t af[8][2][4];
#pragma unroll
        for (int kc = 0; kc < 8; kc++) {
            int c0 = kc * 8 + tig;
#pragma unroll
            for (int mi = 0; mi < 2; mi++) {
                int r0 = mi * 16 + gid;
                af[kc][mi][0] = PTw[r0 * QSTR + c0];
                af[kc][mi][1] = PTw[(r0 + 8) * QSTR + c0];
                af[kc][mi][2] = PTw[r0 * QSTR + c0 + 4];
                af[kc][mi][3] = PTw[(r0 + 8) * QSTR + c0 + 4];
            }
        }
        __syncwarp();   // Q stage consumed; region becomes P^T

        float o[2][8][4];
#pragma unroll
        for (int mi = 0; mi < 2; mi++)
#pragma unroll
            for (int dt = 0; dt < 8; dt++)
#pragma unroll
                for (int r = 0; r < 4; r++) o[mi][dt][r] = 0.f;
        float rs[2][2] = {{0.f, 0.f}, {0.f, 0.f}};

        int q0 = 0;
#pragma unroll
        for (int q = 0; q < 4; q++) {
            const int qn = (q == 0) ? 7 : 6;

            // ---- S quarter: c = Q @ K^T, exp, store P^T ----
#pragma unroll
            for (int ntl = 0; ntl < 7; ntl++) {
                if (ntl >= qn) break;
                const int nt = q0 + ntl;
                float c[2][4];
#pragma unroll
                for (int mi = 0; mi < 2; mi++)
#pragma unroll
                    for (int r = 0; r < 4; r++) c[mi][r] = 0.f;
                const uint32_t* kb = Ku + (nt * 8 + gid) * KSTR + tig;
#pragma unroll
                for (int kc = 0; kc < 8; kc++) {
                    uint32_t b0 = kb[kc * 8];
                    uint32_t b1 = kb[kc * 8 + 4];
#pragma unroll
                    for (int mi = 0; mi < 2; mi++)
                        MMA_TF32(c[mi], af[kc][mi][0], af[kc][mi][1],
                                 af[kc][mi][2], af[kc][mi][3], b0, b1);
                }
                const int j0 = nt * 8 + tig * 2;
                const bool m0 = (j0 < 197), m1 = (j0 + 1 < 197);
                const int cb = ntl * 8 + tig * 2;
#pragma unroll
                for (int mi = 0; mi < 2; mi++) {
                    float p0 = m0 ? __expf(c[mi][0]) : 0.f;
                    float p1 = m1 ? __expf(c[mi][1]) : 0.f;
                    float p2 = m0 ? __expf(c[mi][2]) : 0.f;
                    float p3 = m1 ? __expf(c[mi][3]) : 0.f;
                    rs[mi][0] += p0 + p1;
                    rs[mi][1] += p2 + p3;
                    const int r0 = mi * 16 + gid;
                    PTw[cb * PTSTR + r0]           = f2tf(p0);
                    PTw[(cb + 1) * PTSTR + r0]     = f2tf(p1);
                    PTw[cb * PTSTR + r0 + 8]       = f2tf(p2);
                    PTw[(cb + 1) * PTSTR + r0 + 8] = f2tf(p3);
                }
            }
            __syncwarp();

            // ---- O quarter: o += P @ V ----
#pragma unroll
            for (int ntl = 0; ntl < 7; ntl++) {
                if (ntl >= qn) break;
                const int nt = q0 + ntl;
                uint32_t a[2][4];
#pragma unroll
                for (int mi = 0; mi < 2; mi++) {
                    const int r0 = mi * 16 + gid;
                    a[mi][0] = PTw[(ntl * 8 + tig) * PTSTR + r0];
                    a[mi][1] = PTw[(ntl * 8 + tig) * PTSTR + r0 + 8];
                    a[mi][2] = PTw[(ntl * 8 + tig + 4) * PTSTR + r0];
                    a[mi][3] = PTw[(ntl * 8 + tig + 4) * PTSTR + r0 + 8];
                }
                const uint32_t* vb = Vu + (nt * 8 + tig) * VSTR + gid;
#pragma unroll
                for (int dt = 0; dt < 8; dt++) {
                    uint32_t b0 = vb[dt * 8];
                    uint32_t b1 = vb[4 * VSTR + dt * 8];
#pragma unroll
                    for (int mi = 0; mi < 2; mi++)
                        MMA_TF32(o[mi][dt], a[mi][0], a[mi][1], a[mi][2], a[mi][3],
                                 b0, b1);
                }
            }
            __syncwarp();
            q0 += qn;
        }

        // ---- reduce row sums over tig, normalize, store ----
#pragma unroll
        for (int mi = 0; mi < 2; mi++)
#pragma unroll
            for (int e = 0; e < 2; e++) {
                rs[mi][e] += __shfl_xor_sync(0xffffffffu, rs[mi][e], 1);
                rs[mi][e] += __shfl_xor_sync(0xffffffffu, rs[mi][e], 2);
            }

#pragma unroll
        for (int mi = 0; mi < 2; mi++)
#pragma unroll
            for (int half = 0; half < 2; half++) {
                int row = base + mi * 16 + gid + half * 8;
                if (row < NPF) {
                    float inv = 1.f / rs[mi][half];
                    float* op = attn + (rowbase + 1 + fr * NPF + row) * DMODEL + hoff;
#pragma unroll
                    for (int dt = 0; dt < 8; dt++) {
                        float2 v;
                        v.x = f2tff(o[mi][dt][2 * half]     * inv);
                        v.y = f2tff(o[mi][dt][2 * half + 1] * inv);
                        *reinterpret_cast<float2*>(op + dt * 8 + tig * 2) = v;
                    }
                }
            }
    }
}

// ---------------- cls attention ---------------------------------------------
__global__ __launch_bounds__(256) void cls_attn(
    const float* __restrict__ qkv, float* __restrict__ attn)
{
    const int b   = blockIdx.x / NH;
    const int h   = blockIdx.x % NH;
    const int tid = threadIdx.x;

    __shared__ float qs[64];
    __shared__ float red[8][64];
    __shared__ float redl[8];

    const long rowbase = (long)b * NSEQ;
    const int  hoff    = h * DH;

    if (tid < 64) qs[tid] = qkv[rowbase * QKVC + hoff + tid] * 0.125f;
    __syncthreads();

    float acc[64];
#pragma unroll
    for (int d = 0; d < 64; d++) acc[d] = 0.f;
    float l = 0.f;

    for (int j = tid; j < NSEQ; j += 256) {
        const float* kp = qkv + (rowbase + j) * QKVC + hoff + DMODEL;
        float s0 = 0.f, s1 = 0.f, s2 = 0.f, s3 = 0.f;
#pragma unroll
        for (int d4 = 0; d4 < 16; d4++) {
            float4 kk = *reinterpret_cast<const float4*>(kp + d4 * 4);
            s0 = fmaf(qs[d4 * 4 + 0], kk.x, s0);
            s1 = fmaf(qs[d4 * 4 + 1], kk.y, s1);
            s2 = fmaf(qs[d4 * 4 + 2], kk.z, s2);
            s3 = fmaf(qs[d4 * 4 + 3], kk.w, s3);
        }
        float p = __expf((s0 + s1) + (s2 + s3));
        l += p;
        const float* vp = kp + DMODEL;
#pragma unroll
        for (int d4 = 0; d4 < 16; d4++) {
            float4 vv = *reinterpret_cast<const float4*>(vp + d4 * 4);
            acc[d4 * 4 + 0] = fmaf(p, vv.x, acc[d4 * 4 + 0]);
            acc[d4 * 4 + 1] = fmaf(p, vv.y, acc[d4 * 4 + 1]);
            acc[d4 * 4 + 2] = fmaf(p, vv.z, acc[d4 * 4 + 2]);
            acc[d4 * 4 + 3] = fmaf(p, vv.w, acc[d4 * 4 + 3]);
        }
    }

#pragma unroll
    for (int off = 16; off; off >>= 1) {
        l += __shfl_xor_sync(0xffffffffu, l, off);
#pragma unroll
        for (int d = 0; d < 64; d++)
            acc[d] += __shfl_xor_sync(0xffffffffu, acc[d], off);
    }
    const int warp = tid >> 5, lane = tid & 31;
    if (lane == 0) {
        redl[warp] = l;
#pragma unroll
        for (int d = 0; d < 64; d++) red[warp][d] = acc[d];
    }
    __syncthreads();
    if (tid < 64) {
        float s = 0.f, lt = 0.f;
#pragma unroll
        for (int w = 0; w < 8; w++) { s += red[w][tid]; lt += redl[w]; }
        attn[rowbase * DMODEL + hoff + tid] = f2tff(s / lt);
    }
}

// ---------------- host launch ----------------------------------------------
extern "C" void kernel_launch(void* const* d_in, const int* in_sizes, int n_in,
                              void* d_out, int out_size)
{
    const float* x      = (const float*)d_in[0];
    const float* w_qkv  = (const float*)d_in[1];
    const float* w_proj = (const float*)d_in[2];
    const float* b_proj = (const float*)d_in[3];
    float* out = (float*)d_out;

    float *qkv, *attn, *xr, *wq, *wp;
    cudaGetSymbolAddress((void**)&qkv,  g_qkv);
    cudaGetSymbolAddress((void**)&attn, g_attn);
    cudaGetSymbolAddress((void**)&xr,   g_x);
    cudaGetSymbolAddress((void**)&wq,   g_wq);
    cudaGetSymbolAddress((void**)&wp,   g_wp);

    cudaFuncSetAttribute(gemm_tf32_ca<false>, cudaFuncAttributeMaxDynamicSharedMemorySize, GEMM_SMEM);
    cudaFuncSetAttribute(gemm_tf32_ca<true>,  cudaFuncAttributeMaxDynamicSharedMemorySize, GEMM_SMEM);
    cudaFuncSetAttribute(frame_attn_mma,      cudaFuncAttributeMaxDynamicSharedMemorySize, F_SMEM);

    {
        int n4 = (MROWS * DMODEL) / 4;
        round_tf32<<<(n4 + 255) / 256, 256>>>(x, xr, n4);
        n4 = (DMODEL * QKVC) / 4;
        round_tf32<<<(n4 + 255) / 256, 256>>>(w_qkv, wq, n4);
        n4 = (DMODEL * DMODEL) / 4;
        round_tf32<<<(n4 + 255) / 256, 256>>>(w_proj, wp, n4);
    }

    const int mtiles = (MROWS + BM - 1) / BM;   // 197

    gemm_tf32_ca<false><<<dim3(QKVC / BN, mtiles), 256, GEMM_SMEM>>>(
        xr, wq, nullptr, qkv, MROWS, QKVC, DMODEL);

    frame_attn_mma<<<Bq * NH * NF, 256, F_SMEM>>>(qkv, attn);
    cls_attn<<<Bq * NH, 256>>>(qkv, attn);

    gemm_tf32_ca<true><<<dim3(DMODEL / BN, mtiles), 256, GEMM_SMEM>>>(
        attn, wp, b_proj, out, MROWS, DMODEL, DMODEL);
}

// round 6
// speedup vs baseline: 1.1904x; 1.1904x over previous
#include <cuda_runtime.h>
#include <cstdint>

// ---------------- problem constants ----------------------------------------
#define Bq     16
#define NSEQ   1569            // 1 + 8*196
#define DMODEL 768
#define NH     12
#define DH     64
#define NF     8
#define NPF    196
#define MROWS  (Bq * NSEQ)     // 25104
#define QKVC   (3 * DMODEL)    // 2304

// scratch (no cudaMalloc allowed)
__device__ float g_qkv[(size_t)MROWS * QKVC];     // 231 MB
__device__ float g_attn[(size_t)MROWS * DMODEL];  // 77 MB
__device__ float g_x[(size_t)MROWS * DMODEL];     // tf32-rounded x
__device__ float g_wq[(size_t)DMODEL * QKVC];     // rounded w_qkv
__device__ float g_wp[(size_t)DMODEL * DMODEL];   // rounded w_proj

__device__ __forceinline__ uint32_t f2tf(float x) {
    uint32_t r;
    asm("cvt.rna.tf32.f32 %0, %1;" : "=r"(r) : "f"(x));
    return r;
}
__device__ __forceinline__ float f2tff(float x) { return __uint_as_float(f2tf(x)); }

__device__ __forceinline__ uint32_t s2u(const void* p) {
    return (uint32_t)__cvta_generic_to_shared(p);
}

#define MMA_TF32(c, a0,a1,a2,a3, b0,b1)                                          \
    asm volatile(                                                                 \
        "mma.sync.aligned.m16n8k8.row.col.f32.tf32.tf32.f32 "                     \
        "{%0,%1,%2,%3}, {%4,%5,%6,%7}, {%8,%9}, {%0,%1,%2,%3};"                   \
        : "+f"(c[0]), "+f"(c[1]), "+f"(c[2]), "+f"(c[3])                          \
        : "r"(a0), "r"(a1), "r"(a2), "r"(a3), "r"(b0), "r"(b1))

// ---------------- tf32 pre-round pass ---------------------------------------
__global__ __launch_bounds__(256) void round_tf32(
    const float* __restrict__ in, float* __restrict__ out, int n4)
{
    int i = blockIdx.x * 256 + threadIdx.x;
    if (i < n4) {
        float4 v = reinterpret_cast<const float4*>(in)[i];
        v.x = f2tff(v.x); v.y = f2tff(v.y); v.z = f2tff(v.z); v.w = f2tff(v.w);
        reinterpret_cast<float4*>(out)[i] = v;
    }
}

// ---------------- TF32 GEMM: cp.async 3-stage, 2 CTAs/SM (round-4 exact) ----
#define BM 128
#define BN 128
#define BK 32
#define ASTR 36
#define BSTR 136
#define ABUF (BM * ASTR)
#define BBUF (BK * BSTR)
#define STAGES 3
#define GEMM_SMEM (STAGES * (ABUF + BBUF) * 4)   // 107520 bytes

template <bool BIAS>
__global__ __launch_bounds__(256, 2) void gemm_tf32_ca(
    const float* __restrict__ A, const float* __restrict__ Bmat,
    const float* __restrict__ bias, float* __restrict__ C,
    int Mr, int Nc, int Kd)
{
    extern __shared__ float sm[];
    float* As = sm;
    float* Bs = sm + STAGES * ABUF;

    const int tid  = threadIdx.x;
    const int warp = tid >> 5, lane = tid & 31;
    const int gid  = lane >> 2, tig = lane & 3;
    const int wm   = (warp >> 1) * 32;
    const int wn   = (warp & 1) * 64;
    const int brow = blockIdx.y * BM;
    const int bcol = blockIdx.x * BN;

    float acc[2][8][4];
#pragma unroll
    for (int mi = 0; mi < 2; mi++)
#pragma unroll
        for (int ni = 0; ni < 8; ni++)
#pragma unroll
            for (int r = 0; r < 4; r++) acc[mi][ni][r] = 0.f;

    const int nkt = Kd / BK;

    auto issue = [&](int kt) {
        const int buf = kt % STAGES;
        float* Ab = As + buf * ABUF;
        float* Bb = Bs + buf * BBUF;
#pragma unroll
        for (int i = 0; i < 4; i++) {
            int cid = tid + i * 256;
            int row = cid >> 3, c4 = (cid & 7) << 2;
            const float* src = A + (long)(brow + row) * Kd + kt * BK + c4;
            int sz = (brow + row < Mr) ? 16 : 0;
            asm volatile("cp.async.cg.shared.global [%0], [%1], 16, %2;"
                         :: "r"(s2u(Ab + row * ASTR + c4)), "l"(src), "r"(sz));
        }
#pragma unroll
        for (int i = 0; i < 4; i++) {
            int cid = tid + i * 256;
            int kr = cid >> 5, c4 = (cid & 31) << 2;
            const float* src = Bmat + (long)(kt * BK + kr) * Nc + bcol + c4;
            asm volatile("cp.async.cg.shared.global [%0], [%1], 16;"
                         :: "r"(s2u(Bb + kr * BSTR + c4)), "l"(src));
        }
    };

    auto compute = [&](int buf) {
        const uint32_t* Ab = reinterpret_cast<const uint32_t*>(As + buf * ABUF);
        const uint32_t* Bb = reinterpret_cast<const uint32_t*>(Bs + buf * BBUF);
#pragma unroll
        for (int ks = 0; ks < 4; ks++) {
            const int k0 = ks * 8;
            uint32_t af[2][4], bf[8][2];
#pragma unroll
            for (int mi = 0; mi < 2; mi++) {
                const uint32_t* p = Ab + (wm + mi * 16 + gid) * ASTR + k0 + tig;
                af[mi][0] = p[0];
                af[mi][1] = p[8 * ASTR];
                af[mi][2] = p[4];
                af[mi][3] = p[8 * ASTR + 4];
            }
#pragma unroll
            for (int ni = 0; ni < 8; ni++) {
                const uint32_t* p = Bb + (k0 + tig) * BSTR + wn + ni * 8 + gid;
                bf[ni][0] = p[0];
                bf[ni][1] = p[4 * BSTR];
            }
#pragma unroll
            for (int mi = 0; mi < 2; mi++)
#pragma unroll
                for (int ni = 0; ni < 8; ni++)
                    MMA_TF32(acc[mi][ni], af[mi][0], af[mi][1], af[mi][2], af[mi][3],
                             bf[ni][0], bf[ni][1]);
        }
    };

#pragma unroll
    for (int s = 0; s < STAGES - 1; s++) {
        issue(s);
        asm volatile("cp.async.commit_group;");
    }

#pragma unroll 1
    for (int kt = 0; kt < nkt; kt++) {
        asm volatile("cp.async.wait_group %0;" :: "n"(STAGES - 2));
        __syncthreads();
        compute(kt % STAGES);
        if (kt + STAGES - 1 < nkt) issue(kt + STAGES - 1);
        asm volatile("cp.async.commit_group;");
    }

#pragma unroll
    for (int mi = 0; mi < 2; mi++) {
        int r0 = brow + wm + mi * 16 + gid;
#pragma unroll
        for (int ni = 0; ni < 8; ni++) {
            int c0 = bcol + wn + ni * 8 + tig * 2;
            float bx = 0.f, by = 0.f;
            if (BIAS) { bx = bias[c0]; by = bias[c0 + 1]; }
            if (r0 < Mr) {
                float2 v = make_float2(acc[mi][ni][0] + bx, acc[mi][ni][1] + by);
                *reinterpret_cast<float2*>(C + (long)r0 * Nc + c0) = v;
            }
            if (r0 + 8 < Mr) {
                float2 v = make_float2(acc[mi][ni][2] + bx, acc[mi][ni][3] + by);
                *reinterpret_cast<float2*>(C + (long)(r0 + 8) * Nc + c0) = v;
            }
        }
    }
}

// ---------------- frame attention v3: shuffle-P, 2 CTAs/SM ------------------
// Grid = 3072: two blocks per (b,h,frame). Even block: m16-tiles 0..6, odd:
// 7..12. One tile per warp, single pass. P never touches smem: O-phase
// A-fragments come from quad shuffles of the S-phase accumulators.
// Smem = K + V only (112640 B) -> 2 blocks/SM.
#define KSTR 68
#define VSTR 72
#define F_SMEM ((200 * KSTR + 200 * VSTR) * 4)   // 112640 bytes

__global__ __launch_bounds__(256, 2) void frame_attn_mma(
    const float* __restrict__ qkv, float* __restrict__ attn)
{
    extern __shared__ float smf[];
    float* Ks = smf;              // [200][KSTR]; also Q staging scratch
    float* Vs = smf + 200 * KSTR; // [200][VSTR]

    const int tid  = threadIdx.x;
    const int warp = tid >> 5, lane = tid & 31;
    const int gid  = lane >> 2, tig = lane & 3;

    const int bid2 = blockIdx.x;
    const int half = bid2 & 1;
    const int bid  = bid2 >> 1;          // (b*NH + h)*NF + fr
    const int fr   = bid & 7;
    const int h    = (bid >> 3) % NH;
    const int b    = bid / (NF * NH);

    const int tbase  = half * 7;          // first m16 tile
    const int ntiles = half ? 6 : 7;

    const long rowbase = (long)b * NSEQ;
    const int  hoff    = h * DH;

    const uint32_t* Ku = reinterpret_cast<const uint32_t*>(Ks);
    const uint32_t* Vu = reinterpret_cast<const uint32_t*>(Vs);

    // ---- phase 1: stage this block's Q rows into Ks, coalesced ----
    const int nrows = ntiles * 16;        // 112 or 96
    for (int idx = tid; idx < nrows * 16; idx += 256) {
        int row = idx >> 4;
        int c4  = (idx & 15) << 2;
        int grow = tbase * 16 + row;
        float4 v = make_float4(0.f, 0.f, 0.f, 0.f);
        if (grow < NPF) {
            const float* qp = qkv + (rowbase + 1 + fr * NPF + grow) * QKVC + hoff + c4;
            float4 u = *reinterpret_cast<const float4*>(qp);
            v.x = f2tff(u.x * 0.125f);
            v.y = f2tff(u.y * 0.125f);
            v.z = f2tff(u.z * 0.125f);
            v.w = f2tff(u.w * 0.125f);
        }
        *reinterpret_cast<float4*>(&Ks[row * KSTR + c4]) = v;
    }
    __syncthreads();

    // ---- Q fragments to registers (one m16 tile per warp) ----
    uint32_t af[8][4];
    if (warp < ntiles) {
        const int r0 = warp * 16 + gid;
#pragma unroll
        for (int kc = 0; kc < 8; kc++) {
            int c0 = kc * 8 + tig;
            af[kc][0] = Ku[r0 * KSTR + c0];
            af[kc][1] = Ku[(r0 + 8) * KSTR + c0];
            af[kc][2] = Ku[r0 * KSTR + c0 + 4];
            af[kc][3] = Ku[(r0 + 8) * KSTR + c0 + 4];
        }
    }
    __syncthreads();

    // ---- phase 2: load K/V (197 keys + 3 zero rows) ----
    for (int idx = tid; idx < 200 * 16; idx += 256) {
        int j  = idx >> 4;
        int c4 = (idx & 15) << 2;
        float4 kk = make_float4(0.f, 0.f, 0.f, 0.f);
        float4 vv = make_float4(0.f, 0.f, 0.f, 0.f);
        if (j < 197) {
            int t = (j == 0) ? 0 : (1 + fr * NPF + j - 1);
            const float* src = qkv + (rowbase + t) * QKVC + hoff;
            kk = *reinterpret_cast<const float4*>(src + DMODEL + c4);
            vv = *reinterpret_cast<const float4*>(src + 2 * DMODEL + c4);
            kk.x = f2tff(kk.x); kk.y = f2tff(kk.y); kk.z = f2tff(kk.z); kk.w = f2tff(kk.w);
            vv.x = f2tff(vv.x); vv.y = f2tff(vv.y); vv.z = f2tff(vv.z); vv.w = f2tff(vv.w);
        }
        *reinterpret_cast<float4*>(&Ks[j * KSTR + c4]) = kk;
        *reinterpret_cast<float4*>(&Vs[j * VSTR + c4]) = vv;
    }
    __syncthreads();

    // ---- phase 3: compute (keys in 5 chunks of 5 n-tiles = 40 keys) ----
    if (warp < ntiles) {
        const int tile = tbase + warp;

        float o[8][4];
#pragma unroll
        for (int dt = 0; dt < 8; dt++)
#pragma unroll
            for (int r = 0; r < 4; r++) o[dt][r] = 0.f;
        float rs0 = 0.f, rs1 = 0.f;

        const int src0 = (lane & ~3) | (tig >> 1);   // quad-shuffle sources
        const int src1 = src0 + 2;
        const bool oddt = (tig & 1);

#pragma unroll
        for (int chunk = 0; chunk < 5; chunk++) {
            float c[5][4];
#pragma unroll
            for (int ntl = 0; ntl < 5; ntl++)
#pragma unroll
                for (int r = 0; r < 4; r++) c[ntl][r] = 0.f;

            // S = Q @ K^T for 5 n-tiles
#pragma unroll
            for (int ntl = 0; ntl < 5; ntl++) {
                const int nt = chunk * 5 + ntl;
                const uint32_t* kb = Ku + (nt * 8 + gid) * KSTR + tig;
#pragma unroll
                for (int kc = 0; kc < 8; kc++) {
                    uint32_t b0 = kb[kc * 8];
                    uint32_t b1 = kb[kc * 8 + 4];
                    MMA_TF32(c[ntl], af[kc][0], af[kc][1], af[kc][2], af[kc][3],
                             b0, b1);
                }
            }

            // exp + mask + row sums (tf32-rounded P values)
#pragma unroll
            for (int ntl = 0; ntl < 5; ntl++) {
                const int j0 = (chunk * 5 + ntl) * 8 + tig * 2;
                float p0 = (j0     < 197) ? __expf(c[ntl][0]) : 0.f;
                float p1 = (j0 + 1 < 197) ? __expf(c[ntl][1]) : 0.f;
                float p2 = (j0     < 197) ? __expf(c[ntl][2]) : 0.f;
                float p3 = (j0 + 1 < 197) ? __expf(c[ntl][3]) : 0.f;
                rs0 += p0 + p1;
                rs1 += p2 + p3;
                c[ntl][0] = __uint_as_float(f2tf(p0));
                c[ntl][1] = __uint_as_float(f2tf(p1));
                c[ntl][2] = __uint_as_float(f2tf(p2));
                c[ntl][3] = __uint_as_float(f2tf(p3));
            }

            // O += P @ V : A-fragments of P via quad shuffles
#pragma unroll
            for (int ntl = 0; ntl < 5; ntl++) {
                const int nt = chunk * 5 + ntl;
                float x0 = __shfl_sync(0xffffffffu, c[ntl][0], src0);
                float x1 = __shfl_sync(0xffffffffu, c[ntl][1], src0);
                float x2 = __shfl_sync(0xffffffffu, c[ntl][2], src0);
                float x3 = __shfl_sync(0xffffffffu, c[ntl][3], src0);
                float y0 = __shfl_sync(0xffffffffu, c[ntl][0], src1);
                float y1 = __shfl_sync(0xffffffffu, c[ntl][1], src1);
                float y2 = __shfl_sync(0xffffffffu, c[ntl][2], src1);
                float y3 = __shfl_sync(0xffffffffu, c[ntl][3], src1);
                uint32_t a0 = __float_as_uint(oddt ? x1 : x0); // P[gid][8nt+tig]
                uint32_t a1 = __float_as_uint(oddt ? x3 : x2); // P[gid+8][8nt+tig]
                uint32_t a2 = __float_as_uint(oddt ? y1 : y0); // P[gid][8nt+tig+4]
                uint32_t a3 = __float_as_uint(oddt ? y3 : y2); // P[gid+8][8nt+tig+4]
                const uint32_t* vb = Vu + (nt * 8 + tig) * VSTR + gid;
#pragma unroll
                for (int dt = 0; dt < 8; dt++) {
                    uint32_t b0 = vb[dt * 8];
                    uint32_t b1 = vb[4 * VSTR + dt * 8];
                    MMA_TF32(o[dt], a0, a1, a2, a3, b0, b1);
                }
            }
        }

        // reduce row sums over tig, normalize, store
        rs0 += __shfl_xor_sync(0xffffffffu, rs0, 1);
        rs0 += __shfl_xor_sync(0xffffffffu, rs0, 2);
        rs1 += __shfl_xor_sync(0xffffffffu, rs1, 1);
        rs1 += __shfl_xor_sync(0xffffffffu, rs1, 2);
        const float inv0 = 1.f / rs0;
        const float inv1 = 1.f / rs1;

#pragma unroll
        for (int hh = 0; hh < 2; hh++) {
            int row = tile * 16 + gid + hh * 8;
            if (row < NPF) {
                float inv = hh ? inv1 : inv0;
                float* op = attn + (rowbase + 1 + fr * NPF + row) * DMODEL + hoff;
#pragma unroll
                for (int dt = 0; dt < 8; dt++) {
                    float2 v;
                    v.x = f2tff(o[dt][2 * hh]     * inv);
                    v.y = f2tff(o[dt][2 * hh + 1] * inv);
                    *reinterpret_cast<float2*>(op + dt * 8 + tig * 2) = v;
                }
            }
        }
    }
}

// ---------------- cls attention ---------------------------------------------
__global__ __launch_bounds__(256) void cls_attn(
    const float* __restrict__ qkv, float* __restrict__ attn)
{
    const int b   = blockIdx.x / NH;
    const int h   = blockIdx.x % NH;
    const int tid = threadIdx.x;

    __shared__ float qs[64];
    __shared__ float red[8][64];
    __shared__ float redl[8];

    const long rowbase = (long)b * NSEQ;
    const int  hoff    = h * DH;

    if (tid < 64) qs[tid] = qkv[rowbase * QKVC + hoff + tid] * 0.125f;
    __syncthreads();

    float acc[64];
#pragma unroll
    for (int d = 0; d < 64; d++) acc[d] = 0.f;
    float l = 0.f;

    for (int j = tid; j < NSEQ; j += 256) {
        const float* kp = qkv + (rowbase + j) * QKVC + hoff + DMODEL;
        float s0 = 0.f, s1 = 0.f, s2 = 0.f, s3 = 0.f;
#pragma unroll
        for (int d4 = 0; d4 < 16; d4++) {
            float4 kk = *reinterpret_cast<const float4*>(kp + d4 * 4);
            s0 = fmaf(qs[d4 * 4 + 0], kk.x, s0);
            s1 = fmaf(qs[d4 * 4 + 1], kk.y, s1);
            s2 = fmaf(qs[d4 * 4 + 2], kk.z, s2);
            s3 = fmaf(qs[d4 * 4 + 3], kk.w, s3);
        }
        float p = __expf((s0 + s1) + (s2 + s3));
        l += p;
        const float* vp = kp + DMODEL;
#pragma unroll
        for (int d4 = 0; d4 < 16; d4++) {
            float4 vv = *reinterpret_cast<const float4*>(vp + d4 * 4);
            acc[d4 * 4 + 0] = fmaf(p, vv.x, acc[d4 * 4 + 0]);
            acc[d4 * 4 + 1] = fmaf(p, vv.y, acc[d4 * 4 + 1]);
            acc[d4 * 4 + 2] = fmaf(p, vv.z, acc[d4 * 4 + 2]);
            acc[d4 * 4 + 3] = fmaf(p, vv.w, acc[d4 * 4 + 3]);
        }
    }

#pragma unroll
    for (int off = 16; off; off >>= 1) {
        l += __shfl_xor_sync(0xffffffffu, l, off);
#pragma unroll
        for (int d = 0; d < 64; d++)
            acc[d] += __shfl_xor_sync(0xffffffffu, acc[d], off);
    }
    const int warp = tid >> 5, lane = tid & 31;
    if (lane == 0) {
        redl[warp] = l;
#pragma unroll
        for (int d = 0; d < 64; d++) red[warp][d] = acc[d];
    }
    __syncthreads();
    if (tid < 64) {
        float s = 0.f, lt = 0.f;
#pragma unroll
        for (int w = 0; w < 8; w++) { s += red[w][tid]; lt += redl[w]; }
        attn[rowbase * DMODEL + hoff + tid] = f2tff(s / lt);
    }
}

// ---------------- host launch ----------------------------------------------
extern "C" void kernel_launch(void* const* d_in, const int* in_sizes, int n_in,
                              void* d_out, int out_size)
{
    const float* x      = (const float*)d_in[0];
    const float* w_qkv  = (const float*)d_in[1];
    const float* w_proj = (const float*)d_in[2];
    const float* b_proj = (const float*)d_in[3];
    float* out = (float*)d_out;

    float *qkv, *attn, *xr, *wq, *wp;
    cudaGetSymbolAddress((void**)&qkv,  g_qkv);
    cudaGetSymbolAddress((void**)&attn, g_attn);
    cudaGetSymbolAddress((void**)&xr,   g_x);
    cudaGetSymbolAddress((void**)&wq,   g_wq);
    cudaGetSymbolAddress((void**)&wp,   g_wp);

    cudaFuncSetAttribute(gemm_tf32_ca<false>, cudaFuncAttributeMaxDynamicSharedMemorySize, GEMM_SMEM);
    cudaFuncSetAttribute(gemm_tf32_ca<true>,  cudaFuncAttributeMaxDynamicSharedMemorySize, GEMM_SMEM);
    cudaFuncSetAttribute(frame_attn_mma,      cudaFuncAttributeMaxDynamicSharedMemorySize, F_SMEM);

    {
        int n4 = (MROWS * DMODEL) / 4;
        round_tf32<<<(n4 + 255) / 256, 256>>>(x, xr, n4);
        n4 = (DMODEL * QKVC) / 4;
        round_tf32<<<(n4 + 255) / 256, 256>>>(w_qkv, wq, n4);
        n4 = (DMODEL * DMODEL) / 4;
        round_tf32<<<(n4 + 255) / 256, 256>>>(w_proj, wp, n4);
    }

    const int mtiles = (MROWS + BM - 1) / BM;   // 197

    gemm_tf32_ca<false><<<dim3(QKVC / BN, mtiles), 256, GEMM_SMEM>>>(
        xr, wq, nullptr, qkv, MROWS, QKVC, DMODEL);

    frame_attn_mma<<<Bq * NH * NF * 2, 256, F_SMEM>>>(qkv, attn);
    cls_attn<<<Bq * NH, 256>>>(qkv, attn);

    gemm_tf32_ca<true><<<dim3(DMODEL / BN, mtiles), 256, GEMM_SMEM>>>(
        attn, wp, b_proj, out, MROWS, DMODEL, DMODEL);
}